// round 1
// baseline (speedup 1.0000x reference)
#include <cuda_runtime.h>
#include <math.h>

// ChebyshevDescriptor: N=20000 atoms, K=24 neighbors, RAD_ORDER=16 (17 fns),
// ANG_ORDER=8 (9 fns), output [N, 52] f32 = [rad_un(17) | rad_w(17) | ang_un(9) | ang_w(9)]
//
// Strategy: one warp per atom. Lanes 0..23 own one neighbor each.
// Radial sums via per-term butterfly reductions. Angular: stage per-neighbor
// data in shared, each lane processes ~9 of the 276 (j<k) pairs, register
// accumulate, butterfly reduce.

#define N_ATOMS   20000
#define KNBR      24
#define NPAIR     276
#define RAD_ORDER 16
#define ANG_ORDER 8
#define RAD_CUT   8.0f
#define ANG_CUT   6.5f
#define MIN_CUT   0.55f
#define WARPS_PER_BLOCK 8
#define BLOCK_THREADS   (WARPS_PER_BLOCK * 32)

__device__ __forceinline__ float warp_sum(float v) {
    v += __shfl_xor_sync(0xffffffffu, v, 16);
    v += __shfl_xor_sync(0xffffffffu, v, 8);
    v += __shfl_xor_sync(0xffffffffu, v, 4);
    v += __shfl_xor_sync(0xffffffffu, v, 2);
    v += __shfl_xor_sync(0xffffffffu, v, 1);
    return v;
}

__global__ __launch_bounds__(BLOCK_THREADS)
void cheb_desc_kernel(const float* __restrict__ pos,
                      const int* __restrict__ spec,
                      const int* __restrict__ nbr,
                      float* __restrict__ out) {
    const int lane = threadIdx.x & 31;
    const int w    = threadIdx.x >> 5;               // warp in block
    const int atom = blockIdx.x * WARPS_PER_BLOCK + w;
    if (atom >= N_ATOMS) return;

    __shared__ float s_ux[WARPS_PER_BLOCK][KNBR];
    __shared__ float s_uy[WARPS_PER_BLOCK][KNBR];
    __shared__ float s_uz[WARPS_PER_BLOCK][KNBR];
    __shared__ float s_wa[WARPS_PER_BLOCK][KNBR];    // fca * m_ang
    __shared__ float s_ws[WARPS_PER_BLOCK][KNBR];    // fca * m_ang * sj
    __shared__ float s_res[WARPS_PER_BLOCK][52];

    // central atom position (broadcast load)
    const float px = pos[3 * atom + 0];
    const float py = pos[3 * atom + 1];
    const float pz = pos[3 * atom + 2];

    float x = 0.0f;    // radial Chebyshev argument (0 for inactive lanes -> finite T)
    float wr = 0.0f;   // fc * m_rad
    float wrs = 0.0f;  // fc * m_rad * sj

    if (lane < KNBR) {
        const int j = nbr[atom * KNBR + lane];
        const float dx = pos[3 * j + 0] - px;
        const float dy = pos[3 * j + 1] - py;
        const float dz = pos[3 * j + 2] - pz;
        const float d = sqrtf(dx * dx + dy * dy + dz * dz);
        const float inv = 1.0f / fmaxf(d, 1e-9f);
        const float ux = dx * inv, uy = dy * inv, uz = dz * inv;
        const float sj = (spec[j] != 0) ? 1.0f : -1.0f;   // TYPESPIN = [-1, 1]

        // radial
        const bool m_rad = (d <= RAD_CUT) && (d > MIN_CUT);
        x = 2.0f * (d - MIN_CUT) / (RAD_CUT - MIN_CUT) - 1.0f;
        const float fc = 0.5f * (cospif(d * (1.0f / RAD_CUT)) + 1.0f);
        wr = m_rad ? fc : 0.0f;
        wrs = wr * sj;
        if (!m_rad) x = 0.0f;  // keep recurrence finite when masked (d can be ~17)
        // note: even when m_rad true, x in (-1,1], T bounded.
        // restore correct x for valid-but-out-of-rad-cut? Not needed: wr=0 kills it,
        // and x=0 keeps T small. Matches reference (G = T * fc * mask).

        // angular weights
        const bool m_ang = (d <= ANG_CUT) && (d > MIN_CUT);
        const float fca = 0.5f * (cospif(d * (1.0f / ANG_CUT)) + 1.0f);
        const float wa = m_ang ? fca : 0.0f;

        s_ux[w][lane] = ux;
        s_uy[w][lane] = uy;
        s_uz[w][lane] = uz;
        s_wa[w][lane] = wa;
        s_ws[w][lane] = wa * sj;
    }

    // ---------------- radial: 17 Chebyshev terms, reduce over 24 lanes ----------------
    {
        // t = 0: T = 1
        float su = warp_sum(wr);
        float sw = warp_sum(wrs);
        if (lane == 0) { s_res[w][0] = su; s_res[w][17] = sw; }
        // t = 1: T = x
        su = warp_sum(wr * x);
        sw = warp_sum(wrs * x);
        if (lane == 0) { s_res[w][1] = su; s_res[w][18] = sw; }
        float Tmm = 1.0f, Tm = x;
        #pragma unroll
        for (int t = 2; t <= RAD_ORDER; t++) {
            const float T = 2.0f * x * Tm - Tmm;
            su = warp_sum(wr * T);
            sw = warp_sum(wrs * T);
            if (lane == 0) { s_res[w][t] = su; s_res[w][17 + t] = sw; }
            Tmm = Tm; Tm = T;
        }
    }

    __syncwarp();

    // ---------------- angular: 276 pairs over 32 lanes ----------------
    float accU[ANG_ORDER + 1];
    float accW[ANG_ORDER + 1];
    #pragma unroll
    for (int t = 0; t <= ANG_ORDER; t++) { accU[t] = 0.0f; accW[t] = 0.0f; }

    for (int p = lane; p < NPAIR; p += 32) {
        // triu_indices(24, 1) row-major: find (j,k), j<k from linear p.
        // row starts at C(j) = (47j - j^2)/2; discriminant 2209 - 8p is a
        // perfect square exactly at row boundaries -> floor is exact.
        const float disc = 2209.0f - 8.0f * (float)p;
        const int jj = (int)floorf((47.0f - sqrtf(disc)) * 0.5f);
        const int kk = p - ((47 * jj - jj * jj) >> 1) + jj + 1;

        const float wp  = s_wa[w][jj] * s_wa[w][kk];
        const float wsp = s_ws[w][jj] * s_ws[w][kk];

        float ct = s_ux[w][jj] * s_ux[w][kk]
                 + s_uy[w][jj] * s_uy[w][kk]
                 + s_uz[w][jj] * s_uz[w][kk];
        ct = fminf(fmaxf(ct, -1.0f), 1.0f);

        accU[0] += wp;
        accW[0] += wsp;
        accU[1] += wp * ct;
        accW[1] += wsp * ct;
        float Tmm = 1.0f, Tm = ct;
        #pragma unroll
        for (int t = 2; t <= ANG_ORDER; t++) {
            const float T = 2.0f * ct * Tm - Tmm;
            accU[t] += wp * T;
            accW[t] += wsp * T;
            Tmm = Tm; Tm = T;
        }
    }

    #pragma unroll
    for (int t = 0; t <= ANG_ORDER; t++) {
        const float su = warp_sum(accU[t]);
        const float sw = warp_sum(accW[t]);
        if (lane == 0) { s_res[w][34 + t] = su; s_res[w][43 + t] = sw; }
    }

    __syncwarp();

    // coalesced-ish output write: 52 floats per atom
    float* o = out + (size_t)atom * 52;
    o[lane] = s_res[w][lane];
    if (lane < 20) o[32 + lane] = s_res[w][32 + lane];
}

extern "C" void kernel_launch(void* const* d_in, const int* in_sizes, int n_in,
                              void* d_out, int out_size) {
    const float* positions = (const float*)d_in[0];
    const int* species_idx = (const int*)d_in[1];
    const int* neighbor_idx = (const int*)d_in[2];
    float* out = (float*)d_out;

    const int blocks = (N_ATOMS + WARPS_PER_BLOCK - 1) / WARPS_PER_BLOCK;  // 2500
    cheb_desc_kernel<<<blocks, BLOCK_THREADS>>>(positions, species_idx, neighbor_idx, out);
}

// round 2
// speedup vs baseline: 1.4238x; 1.4238x over previous
#include <cuda_runtime.h>
#include <math.h>

// ChebyshevDescriptor: N=20000 atoms, K=24 neighbors, RAD_ORDER=16 (17 fns),
// ANG_ORDER=8 (9 fns), output [N, 52] f32 = [rad_un(17) | rad_w(17) | ang_un(9) | ang_w(9)]
//
// One warp per atom. Lanes 0..23 own a neighbor. Radial Chebyshev products and
// angular pair accumulations are pre-reduced 32->16 with one shuffle round,
// staged in a per-warp [16 x 60] shared array (column = output coefficient,
// interleaved layout), then 32 reducer lanes sum columns and write straight
// to global memory (coalesced).

#define N_ATOMS   20000
#define KNBR      24
#define NPAIR     276
#define RAD_ORDER 16
#define ANG_ORDER 8
#define RAD_CUT   8.0f
#define ANG_CUT   6.5f
#define MIN_CUT   0.55f
#define WPB       8
#define BT        (WPB * 32)
#define RROWS     16
#define RSTRIDE   60   // floats per row: 240B, 16B-aligned, conflict-free store phases

__global__ __launch_bounds__(BT)
void cheb_desc_kernel(const float* __restrict__ pos,
                      const int* __restrict__ spec,
                      const int* __restrict__ nbr,
                      float* __restrict__ out) {
    const int lane = threadIdx.x & 31;
    const int w    = threadIdx.x >> 5;
    const int atom = blockIdx.x * WPB + w;   // 2500 * 8 == 20000 exactly

    __shared__ float  s_red[WPB][RROWS * RSTRIDE];
    __shared__ float4 s_u4[WPB][KNBR];       // (ux, uy, uz, ws)  with wa = |ws|

    float* red = s_red[w];
    // row pointer for the 16 pre-reduced writer lanes (float2 view)
    float2* rrow = (float2*)(red + lane * RSTRIDE);

    const float px = pos[3 * atom + 0];
    const float py = pos[3 * atom + 1];
    const float pz = pos[3 * atom + 2];

    float x = 0.0f, wr = 0.0f, wrs = 0.0f;   // lanes >= KNBR contribute zeros
    if (lane < KNBR) {
        const int j = nbr[atom * KNBR + lane];
        const float dx = pos[3 * j + 0] - px;
        const float dy = pos[3 * j + 1] - py;
        const float dz = pos[3 * j + 2] - pz;
        const float d  = sqrtf(dx * dx + dy * dy + dz * dz);
        const float inv = 1.0f / fmaxf(d, 1e-9f);
        const float sj = (spec[j] != 0) ? 1.0f : -1.0f;   // TYPESPIN = [-1, 1]

        const bool mr = (d <= RAD_CUT) && (d > MIN_CUT);
        const float fc = 0.5f * (cospif(d * (1.0f / RAD_CUT)) + 1.0f);
        wr  = mr ? fc : 0.0f;
        wrs = wr * sj;
        // zero x when masked keeps T recurrence bounded; wr=0 kills the product,
        // matching the reference's G = T * fc * mask.
        x = mr ? (2.0f * (d - MIN_CUT) * (1.0f / (RAD_CUT - MIN_CUT)) - 1.0f) : 0.0f;

        const bool ma = (d <= ANG_CUT) && (d > MIN_CUT);
        const float fca = 0.5f * (cospif(d * (1.0f / ANG_CUT)) + 1.0f);
        const float wa = ma ? fca : 0.0f;
        s_u4[w][lane] = make_float4(dx * inv, dy * inv, dz * inv, wa * sj);
    }

    // ---------- radial: 17 terms, products + 1 shuffle pre-reduce, store float2 ----------
    {
        // t = 0 (T = 1)
        float y = wr, z = wrs;
        y += __shfl_xor_sync(0xffffffffu, y, 16);
        z += __shfl_xor_sync(0xffffffffu, z, 16);
        if (lane < RROWS) rrow[0] = make_float2(y, z);
        // t = 1 (T = x)
        y = wr * x; z = wrs * x;
        y += __shfl_xor_sync(0xffffffffu, y, 16);
        z += __shfl_xor_sync(0xffffffffu, z, 16);
        if (lane < RROWS) rrow[1] = make_float2(y, z);
        float Tmm = 1.0f, Tm = x;
        #pragma unroll
        for (int t = 2; t <= RAD_ORDER; t++) {
            const float T = 2.0f * x * Tm - Tmm;
            y = wr * T; z = wrs * T;
            y += __shfl_xor_sync(0xffffffffu, y, 16);
            z += __shfl_xor_sync(0xffffffffu, z, 16);
            if (lane < RROWS) rrow[t] = make_float2(y, z);
            Tmm = Tm; Tm = T;
        }
    }

    __syncwarp();   // s_u4 visible to all lanes before angular gathers

    // ---------- angular: 276 pairs over 32 lanes, register accumulate ----------
    float aU[ANG_ORDER + 1];
    float aW[ANG_ORDER + 1];
    #pragma unroll
    for (int t = 0; t <= ANG_ORDER; t++) { aU[t] = 0.0f; aW[t] = 0.0f; }

    #pragma unroll
    for (int i = 0; i < 9; i++) {
        const int p = lane + 32 * i;
        if (p < NPAIR) {
            // triu_indices(24,1) decode: row start C(j) = (47j - j^2)/2;
            // disc is a perfect square exactly at row boundaries -> floor exact.
            const float disc = 2209.0f - 8.0f * (float)p;
            const int jj = (int)floorf((47.0f - sqrtf(disc)) * 0.5f);
            const int kk = p - ((47 * jj - jj * jj) >> 1) + jj + 1;

            const float4 a = s_u4[w][jj];
            const float4 b = s_u4[w][kk];
            const float wsp = a.w * b.w;          // (wa_j sj)(wa_k sk)
            const float wp  = fabsf(wsp);         // wa_j wa_k
            float ct = a.x * b.x + a.y * b.y + a.z * b.z;
            ct = fminf(fmaxf(ct, -1.0f), 1.0f);

            aU[0] += wp;
            aW[0] += wsp;
            aU[1] += wp * ct;
            aW[1] += wsp * ct;
            float Tmm = 1.0f, Tm = ct;
            #pragma unroll
            for (int t = 2; t <= ANG_ORDER; t++) {
                const float T = 2.0f * ct * Tm - Tmm;
                aU[t] += wp * T;
                aW[t] += wsp * T;
                Tmm = Tm; Tm = T;
            }
        }
    }

    // pre-reduce 32->16 and stage: float2 col index 17+t  (float cols 34+2t, 35+2t)
    #pragma unroll
    for (int t = 0; t <= ANG_ORDER; t++) {
        float u = aU[t] + __shfl_xor_sync(0xffffffffu, aU[t], 16);
        float v = aW[t] + __shfl_xor_sync(0xffffffffu, aW[t], 16);
        if (lane < RROWS) rrow[17 + t] = make_float2(u, v);
    }

    __syncwarp();   // all staging visible before column reduction

    // ---------- column reduction: 52 coefficients, write straight to global ----------
    // storage col s for output index c:
    //   c<17:  s=2c         (rad_un t=c)
    //   c<34:  s=2c-33      (rad_w  t=c-17)
    //   c<43:  s=2c-34      (ang_un t=c-34)
    //   c<52:  s=2c-51      (ang_w  t=c-43)
    float* o = out + (size_t)atom * 52;
    {
        const int c = lane;                       // 0..31
        const int s = (c < 17) ? (2 * c) : (2 * c - 33);
        float sum = 0.0f;
        #pragma unroll
        for (int n = 0; n < RROWS; n++) sum += red[n * RSTRIDE + s];
        o[c] = sum;
    }
    if (lane < 20) {
        const int c = 32 + lane;                  // 32..51
        const int s = (c < 34) ? (2 * c - 33) : ((c < 43) ? (2 * c - 34) : (2 * c - 51));
        float sum = 0.0f;
        #pragma unroll
        for (int n = 0; n < RROWS; n++) sum += red[n * RSTRIDE + s];
        o[c] = sum;
    }
}

extern "C" void kernel_launch(void* const* d_in, const int* in_sizes, int n_in,
                              void* d_out, int out_size) {
    const float* positions  = (const float*)d_in[0];
    const int* species_idx  = (const int*)d_in[1];
    const int* neighbor_idx = (const int*)d_in[2];
    float* out = (float*)d_out;

    const int blocks = (N_ATOMS + WPB - 1) / WPB;   // 2500
    cheb_desc_kernel<<<blocks, BT>>>(positions, species_idx, neighbor_idx, out);
}

// round 3
// speedup vs baseline: 1.5348x; 1.0779x over previous
#include <cuda_runtime.h>
#include <math.h>

// ChebyshevDescriptor: N=20000 atoms, K=24 neighbors, RAD_ORDER=16 (17 fns),
// ANG_ORDER=8 (9 fns), output [N, 52] f32 = [rad_un(17) | rad_w(17) | ang_un(9) | ang_w(9)]
//
// One warp per atom. Lanes 0..23 own a neighbor (data stays in registers).
// Angular pairs enumerated by rotation r=1..12: lane j pairs with (j+r) mod 24,
// so only the partner needs a shared load (1 LDS.128/pair). Radial terms and
// angular accumulators pre-reduced 32->16 with one shuffle, staged in a
// per-warp [16 x 54] shared array, then 32 reducer lanes sum columns and
// write straight to global (coalesced).

#define N_ATOMS   20000
#define KNBR      24
#define RAD_ORDER 16
#define ANG_ORDER 8
#define RAD_CUT   8.0f
#define ANG_CUT   6.5f
#define MIN_CUT   0.55f
#define WPB       8
#define BT        (WPB * 32)
#define RROWS     16
#define RSTRIDE   54   // 54 mod 4 == 2 -> 16-lane float2 staging is conflict-free

__global__ __launch_bounds__(BT)
void cheb_desc_kernel(const float* __restrict__ pos,
                      const int* __restrict__ spec,
                      const int* __restrict__ nbr,
                      float* __restrict__ out) {
    const int lane = threadIdx.x & 31;
    const int w    = threadIdx.x >> 5;
    const int atom = blockIdx.x * WPB + w;   // 2500 * 8 == 20000 exactly

    __shared__ __align__(16) float s_red[WPB][RROWS * RSTRIDE];
    __shared__ float4 s_u4[WPB][KNBR];       // (ux, uy, uz, ws), wa = |ws|

    float* red = s_red[w];
    float2* rrow = (float2*)(red + lane * RSTRIDE);   // lanes < 16 write here

    const float px = pos[3 * atom + 0];
    const float py = pos[3 * atom + 1];
    const float pz = pos[3 * atom + 2];

    float x = 0.0f, wr = 0.0f, wrs = 0.0f;   // lanes >= KNBR contribute zeros
    float oux = 0.0f, ouy = 0.0f, ouz = 0.0f, ows = 0.0f;   // own angular data

    if (lane < KNBR) {
        const int j = nbr[atom * KNBR + lane];
        const float dx = pos[3 * j + 0] - px;
        const float dy = pos[3 * j + 1] - py;
        const float dz = pos[3 * j + 2] - pz;
        const float d  = sqrtf(dx * dx + dy * dy + dz * dz);
        const float inv = 1.0f / fmaxf(d, 1e-9f);
        const float sj = (spec[j] != 0) ? 1.0f : -1.0f;   // TYPESPIN = [-1, 1]

        const bool mr = (d <= RAD_CUT) && (d > MIN_CUT);
        const float fc = 0.5f * (cospif(d * (1.0f / RAD_CUT)) + 1.0f);
        wr  = mr ? fc : 0.0f;
        wrs = wr * sj;
        x = mr ? (2.0f * (d - MIN_CUT) * (1.0f / (RAD_CUT - MIN_CUT)) - 1.0f) : 0.0f;

        const bool ma = (d <= ANG_CUT) && (d > MIN_CUT);
        const float fca = 0.5f * (cospif(d * (1.0f / ANG_CUT)) + 1.0f);
        const float wa = ma ? fca : 0.0f;

        oux = dx * inv; ouy = dy * inv; ouz = dz * inv; ows = wa * sj;
        s_u4[w][lane] = make_float4(oux, ouy, ouz, ows);
    }

    // ---------- radial: 17 terms, 32->16 pre-reduce, float2 staging ----------
    {
        float y = wr, z = wrs;
        y += __shfl_xor_sync(0xffffffffu, y, 16);
        z += __shfl_xor_sync(0xffffffffu, z, 16);
        if (lane < RROWS) rrow[0] = make_float2(y, z);
        y = wr * x; z = wrs * x;
        y += __shfl_xor_sync(0xffffffffu, y, 16);
        z += __shfl_xor_sync(0xffffffffu, z, 16);
        if (lane < RROWS) rrow[1] = make_float2(y, z);
        float Tmm = 1.0f, Tm = x;
        #pragma unroll
        for (int t = 2; t <= RAD_ORDER; t++) {
            const float T = 2.0f * x * Tm - Tmm;
            y = wr * T; z = wrs * T;
            y += __shfl_xor_sync(0xffffffffu, y, 16);
            z += __shfl_xor_sync(0xffffffffu, z, 16);
            if (lane < RROWS) rrow[t] = make_float2(y, z);
            Tmm = Tm; Tm = T;
        }
    }

    __syncwarp();   // s_u4 visible before partner gathers

    // ---------- angular: rotation pairs (lane, lane+r mod 24), r = 1..12 ----------
    float aU[ANG_ORDER + 1];
    float aW[ANG_ORDER + 1];
    #pragma unroll
    for (int t = 0; t <= ANG_ORDER; t++) { aU[t] = 0.0f; aW[t] = 0.0f; }

    if (lane < KNBR) {
        #pragma unroll
        for (int r = 1; r <= 12; r++) {
            if (r < 12 || lane < 12) {   // r=12 covers only j=0..11 (avoid double count)
                int k = lane + r;
                if (k >= KNBR) k -= KNBR;
                const float4 b = s_u4[w][k];

                const float wsp = ows * b.w;      // (wa_j sj)(wa_k sk)
                const float wp  = fabsf(wsp);     // wa_j wa_k
                float ct = oux * b.x + ouy * b.y + ouz * b.z;
                ct = fminf(fmaxf(ct, -1.0f), 1.0f);

                aU[0] += wp;
                aW[0] += wsp;
                aU[1] += wp * ct;
                aW[1] += wsp * ct;
                float Tmm = 1.0f, Tm = ct;
                #pragma unroll
                for (int t = 2; t <= ANG_ORDER; t++) {
                    const float T = 2.0f * ct * Tm - Tmm;
                    aU[t] += wp * T;
                    aW[t] += wsp * T;
                    Tmm = Tm; Tm = T;
                }
            }
        }
    }

    // pre-reduce 32->16 and stage: float2 col 17+t
    #pragma unroll
    for (int t = 0; t <= ANG_ORDER; t++) {
        float u = aU[t] + __shfl_xor_sync(0xffffffffu, aU[t], 16);
        float v = aW[t] + __shfl_xor_sync(0xffffffffu, aW[t], 16);
        if (lane < RROWS) rrow[17 + t] = make_float2(u, v);
    }

    __syncwarp();   // staging visible before column reduction

    // ---------- column reduction: 52 coefficients -> global ----------
    // storage col s for output index c:
    //   c<17: s=2c | c<34: s=2c-33 | c<43: s=2c-34 | c<52: s=2c-51
    float* o = out + (size_t)atom * 52;
    {
        const int c = lane;                       // 0..31
        const int s = (c < 17) ? (2 * c) : (2 * c - 33);
        float sum = 0.0f;
        #pragma unroll
        for (int n = 0; n < RROWS; n++) sum += red[n * RSTRIDE + s];
        o[c] = sum;
    }
    if (lane < 20) {
        const int c = 32 + lane;                  // 32..51
        const int s = (c < 34) ? (2 * c - 33) : ((c < 43) ? (2 * c - 34) : (2 * c - 51));
        float sum = 0.0f;
        #pragma unroll
        for (int n = 0; n < RROWS; n++) sum += red[n * RSTRIDE + s];
        o[c] = sum;
    }
}

extern "C" void kernel_launch(void* const* d_in, const int* in_sizes, int n_in,
                              void* d_out, int out_size) {
    const float* positions  = (const float*)d_in[0];
    const int* species_idx  = (const int*)d_in[1];
    const int* neighbor_idx = (const int*)d_in[2];
    float* out = (float*)d_out;

    const int blocks = (N_ATOMS + WPB - 1) / WPB;   // 2500
    cheb_desc_kernel<<<blocks, BT>>>(positions, species_idx, neighbor_idx, out);
}